// round 8
// baseline (speedup 1.0000x reference)
#include <cuda_runtime.h>
#include <math.h>

// Fixed problem shapes
#define BB 8
#define SS 4096
#define HH 1152
#define LL 256
#define HV (HH / 4)    // 288 float4 lanes per row
#define KK 4
#define BPB 4          // buckets per pool block
#define GSZ (HV / BPB) // 72 threads per bucket group
#define NPOOL (LL / BPB * BB)   // 512 pool blocks
#define NBLK (BB + NPOOL)       // 520 total

// Scratch (L2-resident)
__device__ int2 g_meta[BB * LL];   // (offset, non-pad count) per bucket
__device__ int  g_tok[BB * SS];    // token lists (non-pad tokens only)
__device__ int  g_flag[BB];        // per-batch ready flags (memset 0 per replay)

// ---------------------------------------------------------------------------
// Fused kernel: blocks 0..7 = prep (one batch each), blocks 8.. = pool.
// ---------------------------------------------------------------------------
__global__ __launch_bounds__(HV, 4) void fused_kernel(
    const float4* __restrict__ hs,
    const int2* __restrict__ ppi,
    const unsigned char* __restrict__ pad,
    float4* __restrict__ out,
    float* __restrict__ mask,
    float scale) {
    const int t = threadIdx.x;
    const int lane = t & 31;
    const int w = t >> 5;

    __shared__ int s_buf[SS];       // prep: packed kidx ; pool: token list
    __shared__ int s_small[LL];     // prep: c_np
    __shared__ int s_small2[LL];    // prep: c_all
    __shared__ int s_ofs[LL];
    __shared__ int s_cur[LL];
    __shared__ int s_wsum[16];
    __shared__ int s_factor;
    __shared__ int2 s_meta[BPB];

    if (blockIdx.x < BB) {
        // =================== PREP (batch b) ===================
        const int b = blockIdx.x;
        const int2* p = ppi + (long long)b * SS;
        const unsigned char* pb = pad + (long long)b * SS;

        // pass 1: max_x
        int mx = 0;
        for (int s = t; s < SS; s += HV) mx = max(mx, p[s].x);
        #pragma unroll
        for (int off = 16; off > 0; off >>= 1)
            mx = max(mx, __shfl_xor_sync(0xFFFFFFFFu, mx, off));
        if (lane == 0) s_wsum[w] = mx;
        for (int i = t; i < LL; i += HV) { s_small[i] = 0; s_small2[i] = 0; s_cur[i] = 0; }
        __syncthreads();
        if (t == 0) {
            int m = s_wsum[0];
            #pragma unroll
            for (int i = 1; i < 9; i++) m = max(m, s_wsum[i]);
            if (m < 0) m = 0;
            s_factor = (m + 1) / KK;
        }
        __syncthreads();
        const int factor = s_factor;

        // pass 2: kidx + histogram + smem stash
        for (int s = t; s < SS; s += HV) {
            const int2 pv = p[s];
            const bool pdv = pb[s];
            const int x = max(pv.x, 0);
            const int y = max(pv.y, 0);
            const long long kv = (long long)(x / KK)
                               + (long long)factor * (long long)(y / KK);
            const bool valid = (kv >= 0 && kv < LL);
            s_buf[s] = (valid ? (int)kv : 0x8000) | (pdv ? 0x10000 : 0);
            if (valid) {
                atomicAdd(&s_small2[(int)kv], 1);
                if (!pdv) atomicAdd(&s_small[(int)kv], 1);
            }
        }
        __syncthreads();

        // exclusive scan of c_np over 256 buckets (warps 0..7)
        int myc = 0, inc = 0;
        if (t < LL) {
            myc = s_small[t];
            inc = myc;
            #pragma unroll
            for (int d = 1; d < 32; d <<= 1) {
                int up = __shfl_up_sync(0xFFFFFFFFu, inc, d);
                if (lane >= d) inc += up;
            }
            if (lane == 31) s_wsum[w] = inc;
        }
        __syncthreads();
        if (t == 0) {
            int run = 0;
            #pragma unroll
            for (int i = 0; i < 8; i++) { int x = s_wsum[i]; s_wsum[i] = run; run += x; }
        }
        __syncthreads();
        if (t < LL) {
            const int excl = inc - myc + s_wsum[w];
            s_ofs[t] = excl;
            g_meta[b * LL + t] = make_int2(excl, myc);
            if (mask != nullptr)
                mask[(long long)b * LL + t] = (s_small2[t] > 0) ? 1.0f : 0.0f;
        }
        __syncthreads();

        // scatter non-pad tokens (order nondet; pool rank-orders)
        for (int s = t; s < SS; s += HV) {
            const int v = s_buf[s];
            if (!(v & 0x18000)) {  // valid and not padded
                const int kv = v & 0x7FFF;
                const int pos = s_ofs[kv] + atomicAdd(&s_cur[kv], 1);
                g_tok[b * SS + pos] = s;
            }
        }
        __threadfence();
        __syncthreads();
        if (t == 0) {
            asm volatile("st.release.gpu.b32 [%0], %1;" :: "l"(&g_flag[b]), "r"(1) : "memory");
        }
    } else {
        // =================== POOL (4 buckets) ===================
        const int pbi = blockIdx.x - BB;
        const int b = pbi >> 6;            // 64 pool blocks per batch
        const int l0 = (pbi & 63) * BPB;
        const int bl0 = b * LL + l0;

        // wait for this batch's prep
        if (t == 0) {
            unsigned ns = 64;
            while (true) {
                int f;
                asm volatile("ld.acquire.gpu.b32 %0, [%1];" : "=r"(f) : "l"(&g_flag[b]) : "memory");
                if (f) break;
                __nanosleep(ns);
                if (ns < 2048) ns <<= 1;
            }
        }
        __syncthreads();

        if (t < BPB) s_meta[t] = __ldcg(&g_meta[bl0 + t]);
        __syncthreads();

        const int start = s_meta[0].x;
        const int total = s_meta[BPB - 1].x + s_meta[BPB - 1].y - start;

        for (int i = t; i < total; i += HV)
            s_buf[i] = __ldcg(&g_tok[b * SS + start + i]);

        // per-bucket deterministic ordering
        const int k = t / GSZ;
        const int tg = t - k * GSZ;
        const int lo = s_meta[k].x - start;
        const int n = s_meta[k].y;
        int nmax = 0;
        #pragma unroll
        for (int j = 0; j < BPB; j++) nmax = max(nmax, s_meta[j].y);
        __syncthreads();

        if (nmax <= GSZ) {
            int val = 0, r = -1;
            if (tg < n) {
                val = s_buf[lo + tg];
                r = 0;
                for (int j = 0; j < n; j++) r += (s_buf[lo + j] < val);
            }
            __syncthreads();
            if (r >= 0) s_buf[lo + r] = val;
        } else {
            if (tg == 0) {
                for (int i = 1; i < n; i++) {
                    const int key = s_buf[lo + i];
                    int j = i - 1;
                    while (j >= 0 && s_buf[lo + j] > key) {
                        s_buf[lo + j + 1] = s_buf[lo + j];
                        j--;
                    }
                    s_buf[lo + j + 1] = key;
                }
            }
        }
        __syncthreads();

        // back-to-back accumulates
        const float4* base4 = hs + (long long)b * SS * HV + t;
        #pragma unroll
        for (int k2 = 0; k2 < BPB; k2++) {
            const int lo2 = s_meta[k2].x - start;
            const int n2 = s_meta[k2].y;
            float4 a0 = make_float4(0.f, 0.f, 0.f, 0.f);
            float4 a1 = a0, a2 = a0, a3 = a0;
            int i = 0;
            for (; i + 4 <= n2; i += 4) {
                const int q0 = s_buf[lo2 + i],     q1 = s_buf[lo2 + i + 1];
                const int q2 = s_buf[lo2 + i + 2], q3 = s_buf[lo2 + i + 3];
                const float4 x0 = __ldcs(base4 + (long long)q0 * HV);
                const float4 x1 = __ldcs(base4 + (long long)q1 * HV);
                const float4 x2 = __ldcs(base4 + (long long)q2 * HV);
                const float4 x3 = __ldcs(base4 + (long long)q3 * HV);
                a0.x += x0.x; a0.y += x0.y; a0.z += x0.z; a0.w += x0.w;
                a1.x += x1.x; a1.y += x1.y; a1.z += x1.z; a1.w += x1.w;
                a2.x += x2.x; a2.y += x2.y; a2.z += x2.z; a2.w += x2.w;
                a3.x += x3.x; a3.y += x3.y; a3.z += x3.z; a3.w += x3.w;
            }
            for (; i < n2; i++) {
                const float4 x = __ldcs(base4 + (long long)s_buf[lo2 + i] * HV);
                a0.x += x.x; a0.y += x.y; a0.z += x.z; a0.w += x.w;
            }
            float4 r;
            r.x = ((a0.x + a1.x) + (a2.x + a3.x)) * scale;
            r.y = ((a0.y + a1.y) + (a2.y + a3.y)) * scale;
            r.z = ((a0.z + a1.z) + (a2.z + a3.z)) * scale;
            r.w = ((a0.w + a1.w) + (a2.w + a3.w)) * scale;
            out[((long long)(bl0 + k2)) * HV + t] = r;
        }
    }
}

// ---------------------------------------------------------------------------
// Launch: memset flags, then one fused kernel.
// ---------------------------------------------------------------------------
extern "C" void kernel_launch(void* const* d_in, const int* in_sizes, int n_in,
                              void* d_out, int out_size) {
    const float*         hs  = (const float*)d_in[0];
    const int2*          ppi = (const int2*)d_in[1];
    const unsigned char* pad = (const unsigned char*)d_in[2];

    const float scale = sqrtf((float)HH) / (float)(KK * KK);

    float* out  = (float*)d_out;
    float* mask = nullptr;
    const long long pooled_elems = (long long)BB * LL * HH;
    if ((long long)out_size >= pooled_elems + (long long)BB * LL)
        mask = out + pooled_elems;

    void* flag_ptr = nullptr;
    cudaGetSymbolAddress(&flag_ptr, g_flag);
    cudaMemsetAsync(flag_ptr, 0, BB * sizeof(int), 0);

    fused_kernel<<<NBLK, HV>>>((const float4*)hs, ppi, pad,
                               (float4*)out, mask, scale);
}

// round 10
// speedup vs baseline: 1.1675x; 1.1675x over previous
#include <cuda_runtime.h>
#include <math.h>

// Fixed problem shapes
#define BB 8
#define SS 4096
#define HH 1152
#define LL 256
#define HV (HH / 4)     // 288 float4 lanes per row
#define KK 4
#define UPB 2           // buckets per work unit (contiguous CSR range)
#define UNITS_PER_B (LL / UPB)        // 128
#define NUNIT (BB * UNITS_PER_B)      // 1024 work units
#define NBLK 592        // one full wave at 4 blocks/SM on 148 SMs

// Scratch (L2-resident)
__device__ int2 g_meta[BB * LL];   // (offset, non-pad count) per bucket
__device__ int  g_tok[BB * SS];    // token lists (non-pad tokens only)
__device__ unsigned g_ctr;         // work counter (memset 0 per replay)

// ---------------------------------------------------------------------------
// Kernel 1: per batch — max_x, kidx, CSR inverted index, mask.
// ---------------------------------------------------------------------------
__global__ __launch_bounds__(512) void prep_kernel(
    const int2* __restrict__ ppi,
    const unsigned char* __restrict__ pad,
    float* __restrict__ mask) {
    const int b = blockIdx.x;
    const int t = threadIdx.x;
    const int lane = t & 31;
    const int w = t >> 5;

    __shared__ int smax[16];
    __shared__ int s_factor;
    __shared__ int c_np[LL];
    __shared__ int c_all[LL];
    __shared__ int s_ofs[LL];
    __shared__ int s_cur[LL];
    __shared__ int s_wsum[8];

    const int2* p = ppi + (long long)b * SS;
    const unsigned char* pb = pad + (long long)b * SS;

    int2 v[8];
    unsigned char pd[8];
    #pragma unroll
    for (int i = 0; i < 8; i++) v[i] = p[t + i * 512];
    #pragma unroll
    for (int i = 0; i < 8; i++) pd[i] = pb[t + i * 512];

    int mx = 0;
    #pragma unroll
    for (int i = 0; i < 8; i++) mx = max(mx, v[i].x);
    #pragma unroll
    for (int off = 16; off > 0; off >>= 1)
        mx = max(mx, __shfl_xor_sync(0xFFFFFFFFu, mx, off));
    if (lane == 0) smax[w] = mx;
    if (t < LL) { c_np[t] = 0; c_all[t] = 0; s_cur[t] = 0; }
    __syncthreads();
    if (t == 0) {
        int m = smax[0];
        #pragma unroll
        for (int i = 1; i < 16; i++) m = max(m, smax[i]);
        if (m < 0) m = 0;
        s_factor = (m + 1) / KK;
    }
    __syncthreads();
    const int factor = s_factor;

    int ki[8];
    #pragma unroll
    for (int i = 0; i < 8; i++) {
        int x = max(v[i].x, 0);
        int y = max(v[i].y, 0);
        long long kv = (long long)(x / KK) + (long long)factor * (long long)(y / KK);
        ki[i] = (kv >= 0 && kv < LL) ? (int)kv : -1;
        if (ki[i] >= 0) {
            atomicAdd(&c_all[ki[i]], 1);
            if (!pd[i]) atomicAdd(&c_np[ki[i]], 1);
        }
    }
    __syncthreads();

    int myc = 0, inc = 0;
    if (t < LL) {
        myc = c_np[t];
        inc = myc;
        #pragma unroll
        for (int d = 1; d < 32; d <<= 1) {
            int up = __shfl_up_sync(0xFFFFFFFFu, inc, d);
            if (lane >= d) inc += up;
        }
        if (lane == 31) s_wsum[w] = inc;
    }
    __syncthreads();
    if (t == 0) {
        int run = 0;
        #pragma unroll
        for (int i = 0; i < 8; i++) { int x = s_wsum[i]; s_wsum[i] = run; run += x; }
    }
    __syncthreads();
    if (t < LL) {
        const int excl = inc - myc + s_wsum[w];
        s_ofs[t] = excl;
        g_meta[b * LL + t] = make_int2(excl, myc);
        if (mask != nullptr)
            mask[(long long)b * LL + t] = (c_all[t] > 0) ? 1.0f : 0.0f;
    }
    __syncthreads();

    #pragma unroll
    for (int i = 0; i < 8; i++) {
        if (ki[i] >= 0 && !pd[i]) {
            const int pos = s_ofs[ki[i]] + atomicAdd(&s_cur[ki[i]], 1);
            g_tok[b * SS + pos] = t + i * 512;
        }
    }
}

// ---------------------------------------------------------------------------
// Kernel 2: persistent blocks pulling 2-bucket work units from a counter.
// ---------------------------------------------------------------------------
__global__ __launch_bounds__(HV, 4) void pool_kernel(
    const float4* __restrict__ hs,
    float4* __restrict__ out,
    float scale) {
    const int t = threadIdx.x;

    __shared__ int s_list[SS];
    __shared__ int2 s_meta[UPB];
    __shared__ unsigned s_w;

    for (;;) {
        if (t == 0) s_w = atomicAdd(&g_ctr, 1u);
        __syncthreads();          // also fences s_list reuse across iterations
        const unsigned u = s_w;
        if (u >= NUNIT) return;

        const int b = (int)(u / UNITS_PER_B);
        const int l0 = (int)(u % UNITS_PER_B) * UPB;
        const int bl0 = b * LL + l0;

        if (t < UPB) s_meta[t] = __ldg(&g_meta[bl0 + t]);
        __syncthreads();

        const int start = s_meta[0].x;
        const int total = s_meta[UPB - 1].x + s_meta[UPB - 1].y - start;

        for (int i = t; i < total; i += HV)
            s_list[i] = __ldg(&g_tok[b * SS + start + i]);
        __syncthreads();

        // deterministic per-bucket rank ordering (handles any bucket size)
        #pragma unroll
        for (int k = 0; k < UPB; k++) {
            const int lo = s_meta[k].x - start;
            const int n = s_meta[k].y;
            for (int base = 0; base < n; base += HV) {
                const int i = base + t;
                int val = 0, r = -1;
                if (i < n) {
                    val = s_list[lo + i];
                    r = 0;
                    for (int j = 0; j < n; j++) r += (s_list[lo + j] < val);
                }
                __syncthreads();
                if (r >= 0) s_list[lo + r] = val;
            }
        }
        __syncthreads();

        // back-to-back accumulates, no barriers between buckets
        const float4* base4 = hs + (long long)b * SS * HV + t;
        #pragma unroll
        for (int k = 0; k < UPB; k++) {
            const int lo = s_meta[k].x - start;
            const int n = s_meta[k].y;
            float4 a0 = make_float4(0.f, 0.f, 0.f, 0.f);
            float4 a1 = a0, a2 = a0, a3 = a0;
            int i = 0;
            for (; i + 4 <= n; i += 4) {
                const int q0 = s_list[lo + i],     q1 = s_list[lo + i + 1];
                const int q2 = s_list[lo + i + 2], q3 = s_list[lo + i + 3];
                const float4 x0 = __ldcs(base4 + (long long)q0 * HV);
                const float4 x1 = __ldcs(base4 + (long long)q1 * HV);
                const float4 x2 = __ldcs(base4 + (long long)q2 * HV);
                const float4 x3 = __ldcs(base4 + (long long)q3 * HV);
                a0.x += x0.x; a0.y += x0.y; a0.z += x0.z; a0.w += x0.w;
                a1.x += x1.x; a1.y += x1.y; a1.z += x1.z; a1.w += x1.w;
                a2.x += x2.x; a2.y += x2.y; a2.z += x2.z; a2.w += x2.w;
                a3.x += x3.x; a3.y += x3.y; a3.z += x3.z; a3.w += x3.w;
            }
            for (; i < n; i++) {
                const float4 x = __ldcs(base4 + (long long)s_list[lo + i] * HV);
                a0.x += x.x; a0.y += x.y; a0.z += x.z; a0.w += x.w;
            }
            float4 r;
            r.x = ((a0.x + a1.x) + (a2.x + a3.x)) * scale;
            r.y = ((a0.y + a1.y) + (a2.y + a3.y)) * scale;
            r.z = ((a0.z + a1.z) + (a2.z + a3.z)) * scale;
            r.w = ((a0.w + a1.w) + (a2.w + a3.w)) * scale;
            out[((long long)(bl0 + k)) * HV + t] = r;
        }
    }
}

// ---------------------------------------------------------------------------
// Launch: reset counter, prep, persistent pool.
// ---------------------------------------------------------------------------
extern "C" void kernel_launch(void* const* d_in, const int* in_sizes, int n_in,
                              void* d_out, int out_size) {
    const float*         hs  = (const float*)d_in[0];
    const int2*          ppi = (const int2*)d_in[1];
    const unsigned char* pad = (const unsigned char*)d_in[2];

    const float scale = sqrtf((float)HH) / (float)(KK * KK);

    float* out  = (float*)d_out;
    float* mask = nullptr;
    const long long pooled_elems = (long long)BB * LL * HH;
    if ((long long)out_size >= pooled_elems + (long long)BB * LL)
        mask = out + pooled_elems;

    void* ctr_ptr = nullptr;
    cudaGetSymbolAddress(&ctr_ptr, g_ctr);
    cudaMemsetAsync(ctr_ptr, 0, sizeof(unsigned), 0);

    prep_kernel<<<BB, 512>>>(ppi, pad, mask);
    pool_kernel<<<NBLK, HV>>>((const float4*)hs, (float4*)out, scale);
}

// round 11
// speedup vs baseline: 1.2351x; 1.0579x over previous
#include <cuda_runtime.h>
#include <math.h>

// Fixed problem shapes
#define BB 8
#define SS 4096
#define HH 1152
#define LL 256
#define HV (HH / 4)    // 288 float4 lanes per row
#define KK 4
#define BPB 4          // buckets per pool block
#define GSZ (HV / BPB) // 72 threads per bucket group

// Scratch (L2-resident)
__device__ int2 g_meta[BB * LL];   // (offset, non-pad count) per bucket
__device__ int  g_tok[BB * SS];    // token lists (non-pad tokens only)

// ---------------------------------------------------------------------------
// Kernel 1: per batch — max_x, kidx, CSR inverted index, mask.
// ---------------------------------------------------------------------------
__global__ __launch_bounds__(512) void prep_kernel(
    const int2* __restrict__ ppi,
    const unsigned char* __restrict__ pad,
    float* __restrict__ mask) {
    const int b = blockIdx.x;
    const int t = threadIdx.x;
    const int lane = t & 31;
    const int w = t >> 5;

    __shared__ int smax[16];
    __shared__ int s_factor;
    __shared__ int c_np[LL];
    __shared__ int c_all[LL];
    __shared__ int s_ofs[LL];
    __shared__ int s_cur[LL];
    __shared__ int s_wsum[8];

    const int2* p = ppi + (long long)b * SS;
    const unsigned char* pb = pad + (long long)b * SS;

    int2 v[8];
    unsigned char pd[8];
    #pragma unroll
    for (int i = 0; i < 8; i++) v[i] = p[t + i * 512];
    #pragma unroll
    for (int i = 0; i < 8; i++) pd[i] = pb[t + i * 512];

    int mx = 0;
    #pragma unroll
    for (int i = 0; i < 8; i++) mx = max(mx, v[i].x);
    #pragma unroll
    for (int off = 16; off > 0; off >>= 1)
        mx = max(mx, __shfl_xor_sync(0xFFFFFFFFu, mx, off));
    if (lane == 0) smax[w] = mx;
    if (t < LL) { c_np[t] = 0; c_all[t] = 0; s_cur[t] = 0; }
    __syncthreads();
    if (t == 0) {
        int m = smax[0];
        #pragma unroll
        for (int i = 1; i < 16; i++) m = max(m, smax[i]);
        if (m < 0) m = 0;
        s_factor = (m + 1) / KK;
    }
    __syncthreads();
    const int factor = s_factor;

    int ki[8];
    #pragma unroll
    for (int i = 0; i < 8; i++) {
        int x = max(v[i].x, 0);
        int y = max(v[i].y, 0);
        long long kv = (long long)(x / KK) + (long long)factor * (long long)(y / KK);
        ki[i] = (kv >= 0 && kv < LL) ? (int)kv : -1;
        if (ki[i] >= 0) {
            atomicAdd(&c_all[ki[i]], 1);
            if (!pd[i]) atomicAdd(&c_np[ki[i]], 1);
        }
    }
    __syncthreads();

    int myc = 0, inc = 0;
    if (t < LL) {
        myc = c_np[t];
        inc = myc;
        #pragma unroll
        for (int d = 1; d < 32; d <<= 1) {
            int up = __shfl_up_sync(0xFFFFFFFFu, inc, d);
            if (lane >= d) inc += up;
        }
        if (lane == 31) s_wsum[w] = inc;
    }
    __syncthreads();
    if (t == 0) {
        int run = 0;
        #pragma unroll
        for (int i = 0; i < 8; i++) { int x = s_wsum[i]; s_wsum[i] = run; run += x; }
    }
    __syncthreads();
    if (t < LL) {
        const int excl = inc - myc + s_wsum[w];
        s_ofs[t] = excl;
        g_meta[b * LL + t] = make_int2(excl, myc);
        if (mask != nullptr)
            mask[(long long)b * LL + t] = (c_all[t] > 0) ? 1.0f : 0.0f;
    }
    __syncthreads();

    #pragma unroll
    for (int i = 0; i < 8; i++) {
        if (ki[i] >= 0 && !pd[i]) {
            const int pos = s_ofs[ki[i]] + atomicAdd(&s_cur[ki[i]], 1);
            g_tok[b * SS + pos] = t + i * 512;
        }
    }
}

// ---------------------------------------------------------------------------
// Kernel 2: one block per (4 buckets, b). PDL: overlaps launch with prep.
// ---------------------------------------------------------------------------
__global__ __launch_bounds__(HV) void pool_kernel(
    const float4* __restrict__ hs,
    float4* __restrict__ out,
    float scale) {
#if __CUDA_ARCH__ >= 900
    cudaGridDependencySynchronize();
#endif
    const int b = blockIdx.y;
    const int l0 = blockIdx.x * BPB;
    const int bl0 = b * LL + l0;
    const int t = threadIdx.x;

    __shared__ int2 s_meta[BPB];
    __shared__ int s_list[SS];

    if (t < BPB) s_meta[t] = __ldg(&g_meta[bl0 + t]);
    __syncthreads();

    const int start = s_meta[0].x;
    const int total = s_meta[BPB - 1].x + s_meta[BPB - 1].y - start;

    for (int i = t; i < total; i += HV)
        s_list[i] = __ldg(&g_tok[b * SS + start + i]);

    // per-bucket deterministic ordering: group k (72 threads) handles bucket k
    const int k = t / GSZ;
    const int tg = t - k * GSZ;
    const int lo = s_meta[k].x - start;
    const int n = s_meta[k].y;
    int nmax = 0;
    #pragma unroll
    for (int j = 0; j < BPB; j++) nmax = max(nmax, s_meta[j].y);
    __syncthreads();

    if (nmax <= GSZ) {
        int val = 0, r = -1;
        if (tg < n) {
            val = s_list[lo + tg];
            r = 0;
            for (int j = 0; j < n; j++) r += (s_list[lo + j] < val);
        }
        __syncthreads();
        if (r >= 0) s_list[lo + r] = val;
    } else {
        if (tg == 0) {
            for (int i = 1; i < n; i++) {
                const int key = s_list[lo + i];
                int j = i - 1;
                while (j >= 0 && s_list[lo + j] > key) {
                    s_list[lo + j + 1] = s_list[lo + j];
                    j--;
                }
                s_list[lo + j + 1] = key;
            }
        }
    }
    __syncthreads();

    // back-to-back accumulates, no barriers between buckets
    const float4* base4 = hs + (long long)b * SS * HV + t;
    #pragma unroll
    for (int k2 = 0; k2 < BPB; k2++) {
        const int lo2 = s_meta[k2].x - start;
        const int n2 = s_meta[k2].y;
        float4 a0 = make_float4(0.f, 0.f, 0.f, 0.f);
        float4 a1 = a0, a2 = a0, a3 = a0;
        int i = 0;
        for (; i + 4 <= n2; i += 4) {
            const int q0 = s_list[lo2 + i],     q1 = s_list[lo2 + i + 1];
            const int q2 = s_list[lo2 + i + 2], q3 = s_list[lo2 + i + 3];
            const float4 x0 = __ldcs(base4 + (long long)q0 * HV);
            const float4 x1 = __ldcs(base4 + (long long)q1 * HV);
            const float4 x2 = __ldcs(base4 + (long long)q2 * HV);
            const float4 x3 = __ldcs(base4 + (long long)q3 * HV);
            a0.x += x0.x; a0.y += x0.y; a0.z += x0.z; a0.w += x0.w;
            a1.x += x1.x; a1.y += x1.y; a1.z += x1.z; a1.w += x1.w;
            a2.x += x2.x; a2.y += x2.y; a2.z += x2.z; a2.w += x2.w;
            a3.x += x3.x; a3.y += x3.y; a3.z += x3.z; a3.w += x3.w;
        }
        for (; i < n2; i++) {
            const float4 x = __ldcs(base4 + (long long)s_list[lo2 + i] * HV);
            a0.x += x.x; a0.y += x.y; a0.z += x.z; a0.w += x.w;
        }
        float4 r;
        r.x = ((a0.x + a1.x) + (a2.x + a3.x)) * scale;
        r.y = ((a0.y + a1.y) + (a2.y + a3.y)) * scale;
        r.z = ((a0.z + a1.z) + (a2.z + a3.z)) * scale;
        r.w = ((a0.w + a1.w) + (a2.w + a3.w)) * scale;
        out[((long long)(bl0 + k2)) * HV + t] = r;
    }
}

// ---------------------------------------------------------------------------
// Launch: prep, then pool with programmatic dependent launch (overlap).
// ---------------------------------------------------------------------------
extern "C" void kernel_launch(void* const* d_in, const int* in_sizes, int n_in,
                              void* d_out, int out_size) {
    const float*         hs  = (const float*)d_in[0];
    const int2*          ppi = (const int2*)d_in[1];
    const unsigned char* pad = (const unsigned char*)d_in[2];

    const float scale = sqrtf((float)HH) / (float)(KK * KK);

    float* out  = (float*)d_out;
    float* mask = nullptr;
    const long long pooled_elems = (long long)BB * LL * HH;
    if ((long long)out_size >= pooled_elems + (long long)BB * LL)
        mask = out + pooled_elems;

    prep_kernel<<<BB, 512>>>(ppi, pad, mask);

    cudaLaunchConfig_t cfg = {};
    cfg.gridDim = dim3(LL / BPB, BB);
    cfg.blockDim = dim3(HV);
    cfg.dynamicSmemBytes = 0;
    cfg.stream = 0;
    cudaLaunchAttribute attrs[1];
    attrs[0].id = cudaLaunchAttributeProgrammaticStreamSerialization;
    attrs[0].val.programmaticStreamSerializationAllowed = 1;
    cfg.attrs = attrs;
    cfg.numAttrs = 1;
    cudaLaunchKernelEx(&cfg, pool_kernel, (const float4*)hs, (float4*)out, scale);
}